// round 2
// baseline (speedup 1.0000x reference)
#include <cuda_runtime.h>

#define BATCH 128
#define SEQ   256
#define UNITS 128
#define NV    512          // 4*UNITS gate width
#define DEPTH 655
#define KROWS 2620         // 4*DEPTH
#define WREG  64           // Wh rows held in registers per thread

// Precomputed M = W_dense @ Wx  [KROWS][NV], plus row KROWS = b_dense@Wx + b_lstm
__device__ float g_M[(KROWS + 1) * NV];

// ---------------------------------------------------------------------------
// bb row: b_dense @ Wx + b_lstm   (1 block, 512 threads)
// ---------------------------------------------------------------------------
__global__ void prep_bb_kernel(const float* __restrict__ b_dense,
                               const float* __restrict__ Wx,
                               const float* __restrict__ b_lstm) {
    int t = threadIdx.x;  // v in [0,512)
    float acc = 0.f;
#pragma unroll 8
    for (int u = 0; u < UNITS; ++u)
        acc = fmaf(b_dense[u], Wx[u * NV + t], acc);
    g_M[KROWS * NV + t] = acc + b_lstm[t];
}

// ---------------------------------------------------------------------------
// M = W_dense @ Wx.  131 blocks x 20 rows, 512 threads (thread = output col v)
// ---------------------------------------------------------------------------
#define RPB 20
__global__ __launch_bounds__(512) void prep_M_kernel(const float* __restrict__ Wd,
                                                     const float* __restrict__ Wx) {
    __shared__ float wd[RPB * UNITS];  // 10 KB
    const int t = threadIdx.x;
    const int r0 = blockIdx.x * RPB;
    for (int idx = t; idx < RPB * UNITS; idx += 512)
        wd[idx] = Wd[r0 * UNITS + idx];
    __syncthreads();

    float acc[RPB];
#pragma unroll
    for (int r = 0; r < RPB; ++r) acc[r] = 0.f;

    for (int u = 0; u < UNITS; u += 4) {
        float x0 = Wx[(u + 0) * NV + t];
        float x1 = Wx[(u + 1) * NV + t];
        float x2 = Wx[(u + 2) * NV + t];
        float x3 = Wx[(u + 3) * NV + t];
#pragma unroll
        for (int r = 0; r < RPB; ++r) {
            float4 w = *(const float4*)&wd[r * UNITS + u];  // broadcast
            acc[r] = fmaf(w.x, x0, fmaf(w.y, x1, fmaf(w.z, x2, fmaf(w.w, x3, acc[r]))));
        }
    }
#pragma unroll
    for (int r = 0; r < RPB; ++r)
        g_M[(r0 + r) * NV + t] = acc[r];
}

// ---------------------------------------------------------------------------
// context features [B,35] + sequence_length scalar
// ---------------------------------------------------------------------------
__global__ void ctx_kernel(const int* __restrict__ last_rule,
                           const int* __restrict__ move_count,
                           const int* __restrict__ node_count,
                           const int* __restrict__ problem_type,
                           float* __restrict__ out, int out_size) {
    const int b = blockIdx.x, j = threadIdx.x;
    if (j < 35) {
        float v;
        if (j == 0)      v = (float)last_rule[b];
        else if (j == 1) v = (float)move_count[b];
        else if (j == 2) v = (float)node_count[b];
        else             v = (problem_type[b] == (j - 3)) ? 1.f : 0.f;
        out[b * 35 + j] = v;
    }
    const int seq_off = BATCH * 35 + BATCH * UNITS + BATCH * SEQ * UNITS;
    if (b == 0 && j == 63 && out_size > seq_off)
        out[seq_off] = (float)SEQ;
}

// ---------------------------------------------------------------------------
// LSTM: one block per batch row; 512 threads, thread t owns gate column v=t.
// Wh rows [0,WREG) register-resident, rows [WREG,128) in smem.
// xz row for step s+1 gathered from g_M (L2) while step s matvec runs.
// ---------------------------------------------------------------------------
__global__ __launch_bounds__(512, 1) void lstm_kernel(
    const int* __restrict__ bwd, const int* __restrict__ fwd,
    const int* __restrict__ lbwd, const int* __restrict__ lfwd,
    const float* __restrict__ Wh,
    float* __restrict__ out_h,    // [B][S][UNITS]
    float* __restrict__ out_lv) { // [B][UNITS]
    extern __shared__ float sm[];
    float* wh_s   = sm;                          // (128-WREG)*512
    float* xz_s   = wh_s + (UNITS - WREG) * NV;  // 512
    float* gate_s = xz_s + NV;                   // 512
    float* h_s    = gate_s + NV;                 // 128
    float* c_s    = h_s + UNITS;                 // 128
    int*   idx_s  = (int*)(c_s + UNITS);         // 4*SEQ ints

    const int b = blockIdx.x;
    const int t = threadIdx.x;

    // load weights: rows 0..WREG-1 -> registers, rest -> smem (all coalesced)
    float wreg[WREG];
#pragma unroll
    for (int i = 0; i < WREG; ++i) wreg[i] = Wh[i * NV + t];
    for (int i = WREG; i < UNITS; ++i) wh_s[(i - WREG) * NV + t] = Wh[i * NV + t];

    // stage all gather indices with offsets pre-added
    if (t < SEQ) {
        idx_s[t]           = bwd[b * SEQ + t];
        idx_s[SEQ + t]     = DEPTH     + fwd[b * SEQ + t];
        idx_s[2 * SEQ + t] = 2 * DEPTH + lbwd[b * SEQ + t];
        idx_s[3 * SEQ + t] = 3 * DEPTH + lfwd[b * SEQ + t];
    }
    if (t < UNITS) { h_s[t] = 0.f; c_s[t] = 0.f; }
    const float bb = g_M[KROWS * NV + t];
    __syncthreads();

    // xz for s = 0
    xz_s[t] = g_M[idx_s[0] * NV + t] + g_M[idx_s[SEQ] * NV + t] +
              g_M[idx_s[2 * SEQ] * NV + t] + g_M[idx_s[3 * SEQ] * NV + t] + bb;
    __syncthreads();

    const bool is_g = ((t >> 7) == 2);  // gate order i,f,g,o -> tanh for g

    for (int s = 0; s < SEQ; ++s) {
        // prefetch next step's xz components (L2-resident table)
        float m0 = 0.f, m1 = 0.f, m2 = 0.f, m3 = 0.f;
        if (s + 1 < SEQ) {
            m0 = g_M[idx_s[s + 1] * NV + t];
            m1 = g_M[idx_s[SEQ + s + 1] * NV + t];
            m2 = g_M[idx_s[2 * SEQ + s + 1] * NV + t];
            m3 = g_M[idx_s[3 * SEQ + s + 1] * NV + t];
        }

        // z_v = xz_v + h . Wh[:,v]
        float acc = xz_s[t];
#pragma unroll
        for (int i = 0; i < WREG; i += 4) {
            float4 h4 = *(const float4*)(h_s + i);  // warp broadcast
            acc = fmaf(h4.x, wreg[i],     acc);
            acc = fmaf(h4.y, wreg[i + 1], acc);
            acc = fmaf(h4.z, wreg[i + 2], acc);
            acc = fmaf(h4.w, wreg[i + 3], acc);
        }
#pragma unroll
        for (int i = WREG; i < UNITS; i += 4) {
            float4 h4 = *(const float4*)(h_s + i);
            const float* w = wh_s + (i - WREG) * NV + t;
            acc = fmaf(h4.x, w[0],      acc);
            acc = fmaf(h4.y, w[NV],     acc);
            acc = fmaf(h4.z, w[2 * NV], acc);
            acc = fmaf(h4.w, w[3 * NV], acc);
        }

        // activation
        float a = is_g ? tanhf(acc) : __fdividef(1.0f, 1.0f + __expf(-acc));
        gate_s[t] = a;
        __syncthreads();

        if (t < UNITS) {
            float cn = fmaf(gate_s[UNITS + t], c_s[t], gate_s[t] * gate_s[2 * UNITS + t]);
            c_s[t] = cn;
            float hn = gate_s[3 * UNITS + t] * tanhf(cn);
            h_s[t] = hn;
            out_h[(b * SEQ + s) * UNITS + t] = hn;
            if (s == SEQ - 1) out_lv[b * UNITS + t] = hn;
        }
        xz_s[t] = m0 + m1 + m2 + m3 + bb;  // own slot only: no hazard
        __syncthreads();
    }
}

// ---------------------------------------------------------------------------
extern "C" void kernel_launch(void* const* d_in, const int* in_sizes, int n_in,
                              void* d_out, int out_size) {
    const int*   move_count   = (const int*)d_in[0];
    // d_in[1] = moves_remaining (unused by reference)
    const int*   last_rule    = (const int*)d_in[2];
    const int*   node_count   = (const int*)d_in[3];
    const int*   problem_type = (const int*)d_in[4];
    const int*   bwd          = (const int*)d_in[5];
    const int*   fwd          = (const int*)d_in[6];
    const int*   lbwd         = (const int*)d_in[7];
    const int*   lfwd         = (const int*)d_in[8];
    const float* Wd           = (const float*)d_in[9];
    const float* b_dense      = (const float*)d_in[10];
    const float* Wx           = (const float*)d_in[11];
    const float* Wh           = (const float*)d_in[12];
    const float* b_lstm       = (const float*)d_in[13];
    float* out = (float*)d_out;

    const int smem_bytes = ((UNITS - WREG) * NV + NV + NV + UNITS + UNITS) * 4 + 4 * SEQ * 4;
    cudaFuncSetAttribute(lstm_kernel, cudaFuncAttributeMaxDynamicSharedMemorySize, smem_bytes);

    prep_bb_kernel<<<1, NV>>>(b_dense, Wx, b_lstm);
    prep_M_kernel<<<KROWS / RPB, 512>>>(Wd, Wx);
    ctx_kernel<<<BATCH, 64>>>(last_rule, move_count, node_count, problem_type, out, out_size);

    const int off_lv = BATCH * 35;                 // 4480
    const int off_h  = off_lv + BATCH * UNITS;     // 20864
    lstm_kernel<<<BATCH, 512, smem_bytes>>>(bwd, fwd, lbwd, lfwd, Wh,
                                            out + off_h, out + off_lv);
}

// round 3
// speedup vs baseline: 1.0062x; 1.0062x over previous
#include <cuda_runtime.h>

#define BATCH 128
#define SEQ   256
#define UNITS 128
#define NV    512          // 4*UNITS gate width
#define DEPTH 655
#define KROWS 2620         // 4*DEPTH
#define WREG  72           // Wh rows held in registers per thread (mult of 4)
#define SROWS (UNITS - WREG)        // 56 rows in smem
#define RGRP  (WREG / 4)            // 18 register 4-row groups
#define SGRP  (SROWS / 4)           // 14 smem 4-row groups

// Precomputed M = W_dense @ Wx  [KROWS][NV], plus row KROWS = b_dense@Wx + b_lstm
__device__ float g_M[(KROWS + 1) * NV];

// packed f32x2 fma: acc.{lo,hi} += a.{lo,hi} * b.{lo,hi}
#define FMA2(acc, a, b) \
    asm("fma.rn.f32x2 %0, %1, %2, %0;" : "+l"(acc) : "l"(a), "l"(b))

__device__ __forceinline__ unsigned long long pk(float lo, float hi) {
    return (unsigned long long)__float_as_uint(lo) |
           ((unsigned long long)__float_as_uint(hi) << 32);
}
__device__ __forceinline__ float f2lo(unsigned long long v) {
    return __uint_as_float((unsigned)v);
}
__device__ __forceinline__ float f2hi(unsigned long long v) {
    return __uint_as_float((unsigned)(v >> 32));
}
__device__ __forceinline__ float sigmoid_f(float x) {
    return __fdividef(1.f, 1.f + __expf(-x));
}
__device__ __forceinline__ float tanh_f(float x) {
    return 1.f - __fdividef(2.f, __expf(2.f * x) + 1.f);
}

// ---------------------------------------------------------------------------
// bb row: b_dense @ Wx + b_lstm
// ---------------------------------------------------------------------------
__global__ void prep_bb_kernel(const float* __restrict__ b_dense,
                               const float* __restrict__ Wx,
                               const float* __restrict__ b_lstm) {
    int t = threadIdx.x;
    float acc = 0.f;
#pragma unroll 8
    for (int u = 0; u < UNITS; ++u)
        acc = fmaf(b_dense[u], Wx[u * NV + t], acc);
    g_M[KROWS * NV + t] = acc + b_lstm[t];
}

// ---------------------------------------------------------------------------
// M = W_dense @ Wx.  131 blocks x 20 rows, 512 threads (thread = output col v)
// ---------------------------------------------------------------------------
#define RPB 20
__global__ __launch_bounds__(512) void prep_M_kernel(const float* __restrict__ Wd,
                                                     const float* __restrict__ Wx) {
    __shared__ float wd[RPB * UNITS];
    const int t = threadIdx.x;
    const int r0 = blockIdx.x * RPB;
    for (int idx = t; idx < RPB * UNITS; idx += 512)
        wd[idx] = Wd[r0 * UNITS + idx];
    __syncthreads();

    float acc[RPB];
#pragma unroll
    for (int r = 0; r < RPB; ++r) acc[r] = 0.f;

    for (int u = 0; u < UNITS; u += 4) {
        float x0 = Wx[(u + 0) * NV + t];
        float x1 = Wx[(u + 1) * NV + t];
        float x2 = Wx[(u + 2) * NV + t];
        float x3 = Wx[(u + 3) * NV + t];
#pragma unroll
        for (int r = 0; r < RPB; ++r) {
            float4 w = *(const float4*)&wd[r * UNITS + u];
            acc[r] = fmaf(w.x, x0, fmaf(w.y, x1, fmaf(w.z, x2, fmaf(w.w, x3, acc[r]))));
        }
    }
#pragma unroll
    for (int r = 0; r < RPB; ++r)
        g_M[(r0 + r) * NV + t] = acc[r];
}

// ---------------------------------------------------------------------------
// context features [B,35] + sequence_length scalar
// ---------------------------------------------------------------------------
__global__ void ctx_kernel(const int* __restrict__ last_rule,
                           const int* __restrict__ move_count,
                           const int* __restrict__ node_count,
                           const int* __restrict__ problem_type,
                           float* __restrict__ out, int out_size) {
    const int b = blockIdx.x, j = threadIdx.x;
    if (j < 35) {
        float v;
        if (j == 0)      v = (float)last_rule[b];
        else if (j == 1) v = (float)move_count[b];
        else if (j == 2) v = (float)node_count[b];
        else             v = (problem_type[b] == (j - 3)) ? 1.f : 0.f;
        out[b * 35 + j] = v;
    }
    const int seq_off = BATCH * 35 + BATCH * UNITS + BATCH * SEQ * UNITS;
    if (b == 0 && j == 63 && out_size > seq_off)
        out[seq_off] = (float)SEQ;
}

// ---------------------------------------------------------------------------
// LSTM: one block per batch row; 512 threads, thread t owns gate column v=t.
// Wh rows [0,WREG) register-resident as f32x2 pairs; rows [WREG,128) in smem
// packed as 16B groups of 4 row-weights per column (LDS.128, conflict-free).
// Matvec uses fma.rn.f32x2 (2 rows per instruction, 2 independent acc chains).
// ---------------------------------------------------------------------------
// smem layout (bytes):
//   [0, WH_BYTES)            packed Wh smem half: SGRP groups x NV cols x 16B
//   h_s   : 128 floats  (16B aligned)
//   gate_s: 512 floats
//   idx_s : 1024 ints
#define WH_BYTES (SGRP * NV * 16)
#define SMEM_LSTM (WH_BYTES + (UNITS + NV) * 4 + 4 * SEQ * 4)

__global__ __launch_bounds__(512, 1) void lstm_kernel(
    const int* __restrict__ bwd, const int* __restrict__ fwd,
    const int* __restrict__ lbwd, const int* __restrict__ lfwd,
    const float* __restrict__ Wh,
    float* __restrict__ out_h,    // [B][S][UNITS]
    float* __restrict__ out_lv) { // [B][UNITS]
    extern __shared__ unsigned char smraw[];
    ulonglong2* wh_p  = (ulonglong2*)smraw;
    float*      h_s   = (float*)(smraw + WH_BYTES);
    float*      gate_s = h_s + UNITS;
    int*        idx_s = (int*)(gate_s + NV);

    const int b = blockIdx.x;
    const int t = threadIdx.x;

    // ---- weights: rows 0..WREG-1 -> register pairs, rest -> packed smem ----
    unsigned long long wp[RGRP * 2];
#pragma unroll
    for (int i = 0; i < WREG; i += 2)
        wp[i / 2] = pk(Wh[i * NV + t], Wh[(i + 1) * NV + t]);
#pragma unroll
    for (int g = 0; g < SGRP; ++g) {
        int i = WREG + g * 4;
        ulonglong2 v;
        v.x = pk(Wh[i * NV + t],       Wh[(i + 1) * NV + t]);
        v.y = pk(Wh[(i + 2) * NV + t], Wh[(i + 3) * NV + t]);
        wh_p[g * NV + t] = v;
    }

    // ---- stage gather indices with offsets pre-added ----
    if (t < SEQ) {
        idx_s[t]           = bwd[b * SEQ + t];
        idx_s[SEQ + t]     = DEPTH     + fwd[b * SEQ + t];
        idx_s[2 * SEQ + t] = 2 * DEPTH + lbwd[b * SEQ + t];
        idx_s[3 * SEQ + t] = 3 * DEPTH + lfwd[b * SEQ + t];
    }
    if (t < UNITS) h_s[t] = 0.f;
    float c_r = 0.f;  // cell state, register-resident in threads t<128
    const float bb = g_M[KROWS * NV + t];
    __syncthreads();

    // xz for s = 0 (register-resident; it is thread-private)
    float xz_r = g_M[idx_s[0] * NV + t] + g_M[idx_s[SEQ] * NV + t] +
                 g_M[idx_s[2 * SEQ] * NV + t] + g_M[idx_s[3 * SEQ] * NV + t] + bb;

    const bool is_g = ((t >> 7) == 2);  // gate order i,f,g,o -> tanh for g

    for (int s = 0; s < SEQ; ++s) {
        // prefetch next step's xz components (L2-resident table)
        float m0 = 0.f, m1 = 0.f, m2 = 0.f, m3 = 0.f;
        if (s + 1 < SEQ) {
            m0 = g_M[idx_s[s + 1] * NV + t];
            m1 = g_M[idx_s[SEQ + s + 1] * NV + t];
            m2 = g_M[idx_s[2 * SEQ + s + 1] * NV + t];
            m3 = g_M[idx_s[3 * SEQ + s + 1] * NV + t];
        }

        // z_v = xz_v + h . Wh[:,v]   (two independent f32x2 chains)
        unsigned long long acc0 = pk(xz_r, 0.f);
        unsigned long long acc1 = 0ull;
        const ulonglong2* hp = (const ulonglong2*)h_s;
#pragma unroll
        for (int g = 0; g < RGRP; ++g) {
            ulonglong2 hv = hp[g];           // broadcast LDS.128
            FMA2(acc0, hv.x, wp[2 * g]);
            FMA2(acc1, hv.y, wp[2 * g + 1]);
        }
#pragma unroll
        for (int g = 0; g < SGRP; ++g) {
            ulonglong2 hv = hp[RGRP + g];    // broadcast LDS.128
            ulonglong2 wv = wh_p[g * NV + t];
            FMA2(acc0, hv.x, wv.x);
            FMA2(acc1, hv.y, wv.y);
        }
        unsigned long long accs;
        asm("add.rn.f32x2 %0, %1, %2;" : "=l"(accs) : "l"(acc0), "l"(acc1));
        float z = f2lo(accs) + f2hi(accs);

        float a = is_g ? tanh_f(z) : sigmoid_f(z);
        gate_s[t] = a;
        __syncthreads();

        if (t < UNITS) {
            float cn = fmaf(gate_s[UNITS + t], c_r, gate_s[t] * gate_s[2 * UNITS + t]);
            c_r = cn;
            float hn = gate_s[3 * UNITS + t] * tanh_f(cn);
            h_s[t] = hn;
            out_h[(b * SEQ + s) * UNITS + t] = hn;
            if (s == SEQ - 1) out_lv[b * UNITS + t] = hn;
        }
        xz_r = m0 + m1 + m2 + m3 + bb;  // overlaps with tail; no smem hazard
        __syncthreads();
    }
}

// ---------------------------------------------------------------------------
extern "C" void kernel_launch(void* const* d_in, const int* in_sizes, int n_in,
                              void* d_out, int out_size) {
    const int*   move_count   = (const int*)d_in[0];
    // d_in[1] = moves_remaining (unused by reference)
    const int*   last_rule    = (const int*)d_in[2];
    const int*   node_count   = (const int*)d_in[3];
    const int*   problem_type = (const int*)d_in[4];
    const int*   bwd          = (const int*)d_in[5];
    const int*   fwd          = (const int*)d_in[6];
    const int*   lbwd         = (const int*)d_in[7];
    const int*   lfwd         = (const int*)d_in[8];
    const float* Wd           = (const float*)d_in[9];
    const float* b_dense      = (const float*)d_in[10];
    const float* Wx           = (const float*)d_in[11];
    const float* Wh           = (const float*)d_in[12];
    const float* b_lstm       = (const float*)d_in[13];
    float* out = (float*)d_out;

    cudaFuncSetAttribute(lstm_kernel, cudaFuncAttributeMaxDynamicSharedMemorySize,
                         SMEM_LSTM);

    prep_bb_kernel<<<1, NV>>>(b_dense, Wx, b_lstm);
    prep_M_kernel<<<KROWS / RPB, 512>>>(Wd, Wx);
    ctx_kernel<<<BATCH, 64>>>(last_rule, move_count, node_count, problem_type, out, out_size);

    const int off_lv = BATCH * 35;                 // 4480
    const int off_h  = off_lv + BATCH * UNITS;     // 20864
    lstm_kernel<<<BATCH, 512, SMEM_LSTM>>>(bwd, fwd, lbwd, lfwd, Wh,
                                           out + off_h, out + off_lv);
}

// round 4
// speedup vs baseline: 1.3031x; 1.2951x over previous
#include <cuda_runtime.h>

#define BATCH 128
#define SEQ   256
#define UNITS 128
#define NV    512          // 4*UNITS gate width
#define DEPTH 655
#define KROWS 2620         // 4*DEPTH
#define NT    256          // threads per lstm block; thread t owns cols 2t, 2t+1
#define RROWS 96           // Wh rows register-resident per column
#define SROWS (UNITS - RROWS)   // 32 rows in smem
#define RPAIR (RROWS / 2)       // 48 row-pairs per column in registers
#define SGRP4 (SROWS / 4)       // 8 smem groups of 4 rows

// Precomputed M = W_dense @ Wx  [KROWS][NV], plus row KROWS = b_dense@Wx + b_lstm
__device__ float g_M[(KROWS + 1) * NV];

typedef unsigned long long ull;

// packed f32x2 fma: acc.{lo,hi} += a.{lo,hi} * b.{lo,hi}
#define FMA2(acc, a, b) \
    asm("fma.rn.f32x2 %0, %1, %2, %0;" : "+l"(acc) : "l"(a), "l"(b))

__device__ __forceinline__ ull pk(float lo, float hi) {
    return (ull)__float_as_uint(lo) | ((ull)__float_as_uint(hi) << 32);
}
__device__ __forceinline__ float red2(ull a, ull b) {
    ull s;
    asm("add.rn.f32x2 %0, %1, %2;" : "=l"(s) : "l"(a), "l"(b));
    return __uint_as_float((unsigned)s) + __uint_as_float((unsigned)(s >> 32));
}
__device__ __forceinline__ float sigmoid_f(float x) {
    return __fdividef(1.f, 1.f + __expf(-x));
}
__device__ __forceinline__ float tanh_f(float x) {
    return 1.f - __fdividef(2.f, __expf(2.f * x) + 1.f);
}

// ---------------------------------------------------------------------------
// bb row: b_dense @ Wx + b_lstm
// ---------------------------------------------------------------------------
__global__ void prep_bb_kernel(const float* __restrict__ b_dense,
                               const float* __restrict__ Wx,
                               const float* __restrict__ b_lstm) {
    int t = threadIdx.x;
    float acc = 0.f;
#pragma unroll 8
    for (int u = 0; u < UNITS; ++u)
        acc = fmaf(b_dense[u], Wx[u * NV + t], acc);
    g_M[KROWS * NV + t] = acc + b_lstm[t];
}

// ---------------------------------------------------------------------------
// M = W_dense @ Wx.  131 blocks x 20 rows, 512 threads (thread = output col v)
// ---------------------------------------------------------------------------
#define RPB 20
__global__ __launch_bounds__(512) void prep_M_kernel(const float* __restrict__ Wd,
                                                     const float* __restrict__ Wx) {
    __shared__ float wd[RPB * UNITS];
    const int t = threadIdx.x;
    const int r0 = blockIdx.x * RPB;
    for (int idx = t; idx < RPB * UNITS; idx += 512)
        wd[idx] = Wd[r0 * UNITS + idx];
    __syncthreads();

    float acc[RPB];
#pragma unroll
    for (int r = 0; r < RPB; ++r) acc[r] = 0.f;

    for (int u = 0; u < UNITS; u += 4) {
        float x0 = Wx[(u + 0) * NV + t];
        float x1 = Wx[(u + 1) * NV + t];
        float x2 = Wx[(u + 2) * NV + t];
        float x3 = Wx[(u + 3) * NV + t];
#pragma unroll
        for (int r = 0; r < RPB; ++r) {
            float4 w = *(const float4*)&wd[r * UNITS + u];
            acc[r] = fmaf(w.x, x0, fmaf(w.y, x1, fmaf(w.z, x2, fmaf(w.w, x3, acc[r]))));
        }
    }
#pragma unroll
    for (int r = 0; r < RPB; ++r)
        g_M[(r0 + r) * NV + t] = acc[r];
}

// ---------------------------------------------------------------------------
// context features [B,35] + sequence_length scalar
// ---------------------------------------------------------------------------
__global__ void ctx_kernel(const int* __restrict__ last_rule,
                           const int* __restrict__ move_count,
                           const int* __restrict__ node_count,
                           const int* __restrict__ problem_type,
                           float* __restrict__ out, int out_size) {
    const int b = blockIdx.x, j = threadIdx.x;
    if (j < 35) {
        float v;
        if (j == 0)      v = (float)last_rule[b];
        else if (j == 1) v = (float)move_count[b];
        else if (j == 2) v = (float)node_count[b];
        else             v = (problem_type[b] == (j - 3)) ? 1.f : 0.f;
        out[b * 35 + j] = v;
    }
    const int seq_off = BATCH * 35 + BATCH * UNITS + BATCH * SEQ * UNITS;
    if (b == 0 && j == 63 && out_size > seq_off)
        out[seq_off] = (float)SEQ;
}

// ---------------------------------------------------------------------------
// LSTM: one block per batch row; 256 threads, thread t owns gate cols 2t,2t+1.
// Wh rows [0,RROWS) register-resident (f32x2 row-pairs, per column);
// rows [RROWS,128) in smem, one ulonglong2 per (4-row group, column).
// h broadcast loads (LDS.128) feed BOTH columns; matvec is fma.rn.f32x2
// with 2 independent chains per column.
// ---------------------------------------------------------------------------
// smem layout (16B-aligned pieces):
//   wh0 : SGRP4 * NT ulonglong2   (col 2t)    32 KB
//   wh1 : SGRP4 * NT ulonglong2   (col 2t+1)  32 KB
//   h_s : 128 floats
//   gate_s : 512 floats
//   idx_s  : 1024 ints
#define WH_HALF (SGRP4 * NT * 16)
#define SMEM_LSTM (2 * WH_HALF + (UNITS + NV) * 4 + 4 * SEQ * 4)

__global__ __launch_bounds__(NT, 1) void lstm_kernel(
    const int* __restrict__ bwd, const int* __restrict__ fwd,
    const int* __restrict__ lbwd, const int* __restrict__ lfwd,
    const float* __restrict__ Wh,
    float* __restrict__ out_h,    // [B][S][UNITS]
    float* __restrict__ out_lv) { // [B][UNITS]
    extern __shared__ unsigned char smraw[];
    ulonglong2* wh0   = (ulonglong2*)smraw;
    ulonglong2* wh1   = (ulonglong2*)(smraw + WH_HALF);
    float*      h_s   = (float*)(smraw + 2 * WH_HALF);
    float*      gate_s = h_s + UNITS;
    int*        idx_s = (int*)(gate_s + NV);

    const int b = blockIdx.x;
    const int t = threadIdx.x;
    const int c0 = 2 * t;          // first owned gate column

    // ---- weights: rows [0,RROWS) -> register pairs per column ----
    ull wp0[RPAIR], wp1[RPAIR];
#pragma unroll
    for (int p = 0; p < RPAIR; ++p) {
        int i = 2 * p;
        wp0[p] = pk(Wh[i * NV + c0],     Wh[(i + 1) * NV + c0]);
        wp1[p] = pk(Wh[i * NV + c0 + 1], Wh[(i + 1) * NV + c0 + 1]);
    }
    // rows [RROWS,128) -> smem, grouped 4 rows per ulonglong2 per column
#pragma unroll
    for (int g = 0; g < SGRP4; ++g) {
        int i = RROWS + 4 * g;
        ulonglong2 v0, v1;
        v0.x = pk(Wh[i * NV + c0],           Wh[(i + 1) * NV + c0]);
        v0.y = pk(Wh[(i + 2) * NV + c0],     Wh[(i + 3) * NV + c0]);
        v1.x = pk(Wh[i * NV + c0 + 1],       Wh[(i + 1) * NV + c0 + 1]);
        v1.y = pk(Wh[(i + 2) * NV + c0 + 1], Wh[(i + 3) * NV + c0 + 1]);
        wh0[g * NT + t] = v0;
        wh1[g * NT + t] = v1;
    }

    // ---- stage gather indices with offsets pre-added (t covers SEQ=256) ----
    idx_s[t]           = bwd[b * SEQ + t];
    idx_s[SEQ + t]     = DEPTH     + fwd[b * SEQ + t];
    idx_s[2 * SEQ + t] = 2 * DEPTH + lbwd[b * SEQ + t];
    idx_s[3 * SEQ + t] = 3 * DEPTH + lfwd[b * SEQ + t];
    if (t < UNITS) h_s[t] = 0.f;
    float c_r = 0.f;  // cell state, register-resident in threads t<128
    const float2 bb = *(const float2*)&g_M[KROWS * NV + c0];
    __syncthreads();

    // xz for s = 0 (both columns, register-resident)
    float2 xz;
    {
        float2 a = *(const float2*)&g_M[idx_s[0] * NV + c0];
        float2 d = *(const float2*)&g_M[idx_s[SEQ] * NV + c0];
        float2 e = *(const float2*)&g_M[idx_s[2 * SEQ] * NV + c0];
        float2 f = *(const float2*)&g_M[idx_s[3 * SEQ] * NV + c0];
        xz.x = a.x + d.x + e.x + f.x + bb.x;
        xz.y = a.y + d.y + e.y + f.y + bb.y;
    }

    const bool is_g = ((c0 >> 7) == 2);  // gate order i,f,g,o; both cols same bucket

    for (int s = 0; s < SEQ; ++s) {
        // prefetch next step's xz components (L2-resident table, float2 = 2 cols)
        float2 m0 = {0.f, 0.f}, m1 = m0, m2 = m0, m3 = m0;
        if (s + 1 < SEQ) {
            m0 = *(const float2*)&g_M[idx_s[s + 1] * NV + c0];
            m1 = *(const float2*)&g_M[idx_s[SEQ + s + 1] * NV + c0];
            m2 = *(const float2*)&g_M[idx_s[2 * SEQ + s + 1] * NV + c0];
            m3 = *(const float2*)&g_M[idx_s[3 * SEQ + s + 1] * NV + c0];
        }

        // z_v = xz_v + h . Wh[:,v] for v = c0, c0+1
        ull a00 = pk(xz.x, 0.f), a01 = 0ull;   // col c0, 2 chains
        ull a10 = pk(xz.y, 0.f), a11 = 0ull;   // col c0+1
        const ulonglong2* hp = (const ulonglong2*)h_s;
#pragma unroll
        for (int g = 0; g < RPAIR / 2; ++g) {  // 24 groups x 4 rows = 96 rows
            ulonglong2 hv = hp[g];             // broadcast LDS.128: serves both cols
            FMA2(a00, hv.x, wp0[2 * g]);
            FMA2(a01, hv.y, wp0[2 * g + 1]);
            FMA2(a10, hv.x, wp1[2 * g]);
            FMA2(a11, hv.y, wp1[2 * g + 1]);
        }
#pragma unroll
        for (int g = 0; g < SGRP4; ++g) {      // 8 groups x 4 rows = 32 rows
            ulonglong2 hv = hp[RPAIR / 2 + g]; // broadcast LDS.128
            ulonglong2 w0 = wh0[g * NT + t];
            ulonglong2 w1 = wh1[g * NT + t];
            FMA2(a00, hv.x, w0.x);
            FMA2(a01, hv.y, w0.y);
            FMA2(a10, hv.x, w1.x);
            FMA2(a11, hv.y, w1.y);
        }
        float z0 = red2(a00, a01);
        float z1 = red2(a10, a11);

        float act0 = is_g ? tanh_f(z0) : sigmoid_f(z0);
        float act1 = is_g ? tanh_f(z1) : sigmoid_f(z1);
        *(float2*)&gate_s[c0] = make_float2(act0, act1);
        __syncthreads();

        if (t < UNITS) {
            float cn = fmaf(gate_s[UNITS + t], c_r, gate_s[t] * gate_s[2 * UNITS + t]);
            c_r = cn;
            float hn = gate_s[3 * UNITS + t] * tanh_f(cn);
            h_s[t] = hn;
            out_h[(b * SEQ + s) * UNITS + t] = hn;
            if (s == SEQ - 1) out_lv[b * UNITS + t] = hn;
        }
        xz.x = m0.x + m1.x + m2.x + m3.x + bb.x;
        xz.y = m0.y + m1.y + m2.y + m3.y + bb.y;
        __syncthreads();
    }
}

// ---------------------------------------------------------------------------
extern "C" void kernel_launch(void* const* d_in, const int* in_sizes, int n_in,
                              void* d_out, int out_size) {
    const int*   move_count   = (const int*)d_in[0];
    // d_in[1] = moves_remaining (unused by reference)
    const int*   last_rule    = (const int*)d_in[2];
    const int*   node_count   = (const int*)d_in[3];
    const int*   problem_type = (const int*)d_in[4];
    const int*   bwd          = (const int*)d_in[5];
    const int*   fwd          = (const int*)d_in[6];
    const int*   lbwd         = (const int*)d_in[7];
    const int*   lfwd         = (const int*)d_in[8];
    const float* Wd           = (const float*)d_in[9];
    const float* b_dense      = (const float*)d_in[10];
    const float* Wx           = (const float*)d_in[11];
    const float* Wh           = (const float*)d_in[12];
    const float* b_lstm       = (const float*)d_in[13];
    float* out = (float*)d_out;

    cudaFuncSetAttribute(lstm_kernel, cudaFuncAttributeMaxDynamicSharedMemorySize,
                         SMEM_LSTM);

    prep_bb_kernel<<<1, NV>>>(b_dense, Wx, b_lstm);
    prep_M_kernel<<<KROWS / RPB, 512>>>(Wd, Wx);
    ctx_kernel<<<BATCH, 64>>>(last_rule, move_count, node_count, problem_type, out, out_size);

    const int off_lv = BATCH * 35;                 // 4480
    const int off_h  = off_lv + BATCH * UNITS;     // 20864
    lstm_kernel<<<BATCH, NT, SMEM_LSTM>>>(bwd, fwd, lbwd, lfwd, Wh,
                                          out + off_h, out + off_lv);
}

// round 5
// speedup vs baseline: 1.4143x; 1.0853x over previous
#include <cuda_runtime.h>

#define BATCH 128
#define SEQ   256
#define UNITS 128
#define NV    512          // 4*UNITS gate width
#define DEPTH 655
#define KROWS 2620         // 4*DEPTH
#define NT    256          // threads per lstm block
#define RROWS 96           // Wh rows register-resident per column
#define SROWS (UNITS - RROWS)   // 32 rows in smem
#define RPAIR (RROWS / 2)       // 48 row-pairs per column in registers
#define SGRP4 (SROWS / 4)       // 8 smem groups of 4 rows

// Precomputed M = W_dense @ Wx  [KROWS][NV], plus row KROWS = b_dense@Wx + b_lstm
__device__ float g_M[(KROWS + 1) * NV];

typedef unsigned long long ull;

// packed f32x2 fma: acc.{lo,hi} += a.{lo,hi} * b.{lo,hi}
#define FMA2(acc, a, b) \
    asm("fma.rn.f32x2 %0, %1, %2, %0;" : "+l"(acc) : "l"(a), "l"(b))

__device__ __forceinline__ ull pk(float lo, float hi) {
    return (ull)__float_as_uint(lo) | ((ull)__float_as_uint(hi) << 32);
}
__device__ __forceinline__ float red2(ull a, ull b) {
    ull s;
    asm("add.rn.f32x2 %0, %1, %2;" : "=l"(s) : "l"(a), "l"(b));
    return __uint_as_float((unsigned)s) + __uint_as_float((unsigned)(s >> 32));
}
__device__ __forceinline__ float sigmoid_f(float x) {
    return __fdividef(1.f, 1.f + __expf(-x));
}
__device__ __forceinline__ float tanh_f(float x) {
    return 1.f - __fdividef(2.f, __expf(2.f * x) + 1.f);
}

// ---------------------------------------------------------------------------
// bb row: b_dense @ Wx + b_lstm
// ---------------------------------------------------------------------------
__global__ void prep_bb_kernel(const float* __restrict__ b_dense,
                               const float* __restrict__ Wx,
                               const float* __restrict__ b_lstm) {
    int t = threadIdx.x;
    float acc = 0.f;
#pragma unroll 8
    for (int u = 0; u < UNITS; ++u)
        acc = fmaf(b_dense[u], Wx[u * NV + t], acc);
    g_M[KROWS * NV + t] = acc + b_lstm[t];
}

// ---------------------------------------------------------------------------
// M = W_dense @ Wx.  131 blocks x 20 rows, 512 threads (thread = output col v)
// ---------------------------------------------------------------------------
#define RPB 20
__global__ __launch_bounds__(512) void prep_M_kernel(const float* __restrict__ Wd,
                                                     const float* __restrict__ Wx) {
    __shared__ float wd[RPB * UNITS];
    const int t = threadIdx.x;
    const int r0 = blockIdx.x * RPB;
    for (int idx = t; idx < RPB * UNITS; idx += 512)
        wd[idx] = Wd[r0 * UNITS + idx];
    __syncthreads();

    float acc[RPB];
#pragma unroll
    for (int r = 0; r < RPB; ++r) acc[r] = 0.f;

    for (int u = 0; u < UNITS; u += 4) {
        float x0 = Wx[(u + 0) * NV + t];
        float x1 = Wx[(u + 1) * NV + t];
        float x2 = Wx[(u + 2) * NV + t];
        float x3 = Wx[(u + 3) * NV + t];
#pragma unroll
        for (int r = 0; r < RPB; ++r) {
            float4 w = *(const float4*)&wd[r * UNITS + u];
            acc[r] = fmaf(w.x, x0, fmaf(w.y, x1, fmaf(w.z, x2, fmaf(w.w, x3, acc[r]))));
        }
    }
#pragma unroll
    for (int r = 0; r < RPB; ++r)
        g_M[(r0 + r) * NV + t] = acc[r];
}

// ---------------------------------------------------------------------------
// context features [B,35] + sequence_length scalar
// ---------------------------------------------------------------------------
__global__ void ctx_kernel(const int* __restrict__ last_rule,
                           const int* __restrict__ move_count,
                           const int* __restrict__ node_count,
                           const int* __restrict__ problem_type,
                           float* __restrict__ out, int out_size) {
    const int b = blockIdx.x, j = threadIdx.x;
    if (j < 35) {
        float v;
        if (j == 0)      v = (float)last_rule[b];
        else if (j == 1) v = (float)move_count[b];
        else if (j == 2) v = (float)node_count[b];
        else             v = (problem_type[b] == (j - 3)) ? 1.f : 0.f;
        out[b * 35 + j] = v;
    }
    const int seq_off = BATCH * 35 + BATCH * UNITS + BATCH * SEQ * UNITS;
    if (b == 0 && j == 63 && out_size > seq_off)
        out[seq_off] = (float)SEQ;
}

// ---------------------------------------------------------------------------
// LSTM: one block per batch row; 256 threads. Warp w covers elements
// [16w, 16w+16). Lane l<16 owns element e=16w+l with gate columns (e, e+256)
// = (i, g); lane l+16 owns (e+128, e+384) = (f, o). After activations, two
// shfl.xor(16) bring f,o to the (i,g) lane which computes c,h in registers.
// h published via ping-pong smem buffers -> ONE __syncthreads per step.
// Wh rows [0,RROWS) register-resident (f32x2 pairs per column); rows
// [RROWS,128) in smem (ulonglong2 per 4-row group per column).
// ---------------------------------------------------------------------------
#define WH_HALF (SGRP4 * NT * 16)      // 32 KB per column-set
#define SMEM_LSTM (2 * WH_HALF + 2 * UNITS * 4 + 4 * SEQ * 4)

__global__ __launch_bounds__(NT, 1) void lstm_kernel(
    const int* __restrict__ bwd, const int* __restrict__ fwd,
    const int* __restrict__ lbwd, const int* __restrict__ lfwd,
    const float* __restrict__ Wh,
    float* __restrict__ out_h,    // [B][S][UNITS]
    float* __restrict__ out_lv) { // [B][UNITS]
    extern __shared__ unsigned char smraw[];
    ulonglong2* whA = (ulonglong2*)smraw;
    ulonglong2* whB = (ulonglong2*)(smraw + WH_HALF);
    float*      h0  = (float*)(smraw + 2 * WH_HALF);
    float*      h1  = h0 + UNITS;
    int*        idx_s = (int*)(h1 + UNITS);

    const int b = blockIdx.x;
    const int t = threadIdx.x;
    const int l = t & 31;
    const int role = l >> 4;                 // 0: (i,g) owner, 1: (f,o) owner
    const int e  = (t >> 5) * 16 + (l & 15); // element in [0,128)
    const int cA = e + role * 128;           // i (role0) / f (role1)
    const int cB = cA + 256;                 // g (role0) / o (role1)

    // ---- weights: rows [0,RROWS) -> register pairs per column ----
    ull wA[RPAIR], wB[RPAIR];
#pragma unroll
    for (int p = 0; p < RPAIR; ++p) {
        int i = 2 * p;
        wA[p] = pk(Wh[i * NV + cA], Wh[(i + 1) * NV + cA]);
        wB[p] = pk(Wh[i * NV + cB], Wh[(i + 1) * NV + cB]);
    }
    // rows [RROWS,128) -> smem, 4 rows per ulonglong2 per column
#pragma unroll
    for (int g = 0; g < SGRP4; ++g) {
        int i = RROWS + 4 * g;
        ulonglong2 vA, vB;
        vA.x = pk(Wh[i * NV + cA],       Wh[(i + 1) * NV + cA]);
        vA.y = pk(Wh[(i + 2) * NV + cA], Wh[(i + 3) * NV + cA]);
        vB.x = pk(Wh[i * NV + cB],       Wh[(i + 1) * NV + cB]);
        vB.y = pk(Wh[(i + 2) * NV + cB], Wh[(i + 3) * NV + cB]);
        whA[g * NT + t] = vA;
        whB[g * NT + t] = vB;
    }

    // ---- stage gather indices with offsets pre-added (t covers SEQ=256) ----
    idx_s[t]           = bwd[b * SEQ + t];
    idx_s[SEQ + t]     = DEPTH     + fwd[b * SEQ + t];
    idx_s[2 * SEQ + t] = 2 * DEPTH + lbwd[b * SEQ + t];
    idx_s[3 * SEQ + t] = 3 * DEPTH + lfwd[b * SEQ + t];
    if (t < UNITS) h0[t] = 0.f;
    float c_r = 0.f, h_last = 0.f;
    const float bbA = g_M[KROWS * NV + cA];
    const float bbB = g_M[KROWS * NV + cB];
    __syncthreads();

    // xz for s = 0 (both columns, registers)
    float xzA = g_M[idx_s[0] * NV + cA] + g_M[idx_s[SEQ] * NV + cA] +
                g_M[idx_s[2 * SEQ] * NV + cA] + g_M[idx_s[3 * SEQ] * NV + cA] + bbA;
    float xzB = g_M[idx_s[0] * NV + cB] + g_M[idx_s[SEQ] * NV + cB] +
                g_M[idx_s[2 * SEQ] * NV + cB] + g_M[idx_s[3 * SEQ] * NV + cB] + bbB;

    for (int s = 0; s < SEQ; ++s) {
        // prefetch next step's xz components (L2-resident table)
        const int sn = (s + 1 < SEQ) ? s + 1 : s;
        float mA0 = g_M[idx_s[sn] * NV + cA];
        float mA1 = g_M[idx_s[SEQ + sn] * NV + cA];
        float mA2 = g_M[idx_s[2 * SEQ + sn] * NV + cA];
        float mA3 = g_M[idx_s[3 * SEQ + sn] * NV + cA];
        float mB0 = g_M[idx_s[sn] * NV + cB];
        float mB1 = g_M[idx_s[SEQ + sn] * NV + cB];
        float mB2 = g_M[idx_s[2 * SEQ + sn] * NV + cB];
        float mB3 = g_M[idx_s[3 * SEQ + sn] * NV + cB];

        // z = xz + h . Wh[:,c]  for cA and cB (4 independent f32x2 chains)
        const ulonglong2* hp = (const ulonglong2*)((s & 1) ? h1 : h0);
        ull aA0 = pk(xzA, 0.f), aA1 = 0ull;
        ull aB0 = pk(xzB, 0.f), aB1 = 0ull;
#pragma unroll
        for (int g = 0; g < RPAIR / 2; ++g) {   // 24 groups x 4 rows = 96 rows
            ulonglong2 hv = hp[g];              // broadcast LDS.128
            FMA2(aA0, hv.x, wA[2 * g]);
            FMA2(aA1, hv.y, wA[2 * g + 1]);
            FMA2(aB0, hv.x, wB[2 * g]);
            FMA2(aB1, hv.y, wB[2 * g + 1]);
        }
#pragma unroll
        for (int g = 0; g < SGRP4; ++g) {       // 8 groups x 4 rows = 32 rows
            ulonglong2 hv = hp[RPAIR / 2 + g];  // broadcast LDS.128
            ulonglong2 vA = whA[g * NT + t];
            ulonglong2 vB = whB[g * NT + t];
            FMA2(aA0, hv.x, vA.x);
            FMA2(aA1, hv.y, vA.y);
            FMA2(aB0, hv.x, vB.x);
            FMA2(aB1, hv.y, vB.y);
        }
        float zA = red2(aA0, aA1);
        float zB = red2(aB0, aB1);

        // activations: cA is i or f -> sigmoid; cB is g (tanh) or o (sigmoid)
        float actA = sigmoid_f(zA);
        float actB = role ? sigmoid_f(zB) : tanh_f(zB);

        // exchange: (i,g) lane receives (f,o) from lane+16
        float xf = __shfl_xor_sync(0xffffffffu, actA, 16);
        float xo = __shfl_xor_sync(0xffffffffu, actB, 16);

        float* hw = (s & 1) ? h0 : h1;
        if (role == 0) {
            float cn = fmaf(xf, c_r, actA * actB);   // f*c + i*g
            c_r = cn;
            float hn = xo * tanh_f(cn);
            hw[e] = hn;
            out_h[(b * SEQ + s) * UNITS + e] = hn;
            h_last = hn;
        }
        xzA = mA0 + mA1 + mA2 + mA3 + bbA;
        xzB = mB0 + mB1 + mB2 + mB3 + bbB;
        __syncthreads();
    }
    if (role == 0) out_lv[b * UNITS + e] = h_last;
}

// ---------------------------------------------------------------------------
extern "C" void kernel_launch(void* const* d_in, const int* in_sizes, int n_in,
                              void* d_out, int out_size) {
    const int*   move_count   = (const int*)d_in[0];
    // d_in[1] = moves_remaining (unused by reference)
    const int*   last_rule    = (const int*)d_in[2];
    const int*   node_count   = (const int*)d_in[3];
    const int*   problem_type = (const int*)d_in[4];
    const int*   bwd          = (const int*)d_in[5];
    const int*   fwd          = (const int*)d_in[6];
    const int*   lbwd         = (const int*)d_in[7];
    const int*   lfwd         = (const int*)d_in[8];
    const float* Wd           = (const float*)d_in[9];
    const float* b_dense      = (const float*)d_in[10];
    const float* Wx           = (const float*)d_in[11];
    const float* Wh           = (const float*)d_in[12];
    const float* b_lstm       = (const float*)d_in[13];
    float* out = (float*)d_out;

    cudaFuncSetAttribute(lstm_kernel, cudaFuncAttributeMaxDynamicSharedMemorySize,
                         SMEM_LSTM);

    prep_bb_kernel<<<1, NV>>>(b_dense, Wx, b_lstm);
    prep_M_kernel<<<KROWS / RPB, 512>>>(Wd, Wx);
    ctx_kernel<<<BATCH, 64>>>(last_rule, move_count, node_count, problem_type, out, out_size);

    const int off_lv = BATCH * 35;                 // 4480
    const int off_h  = off_lv + BATCH * UNITS;     // 20864
    lstm_kernel<<<BATCH, NT, SMEM_LSTM>>>(bwd, fwd, lbwd, lfwd, Wh,
                                          out + off_h, out + off_lv);
}